// round 16
// baseline (speedup 1.0000x reference)
#include <cuda_runtime.h>
#include <math.h>

#define BATCH    64
#define DIN      1024
#define DOUT     1024
#define O4S      (DOUT / 4)          // 256 float4s along o
#define OSPLITS  37                  // 17 chunks of 8 float4 + 20 chunks of 6
#define NC8      17                  // chunks with C=8 (128B, line-aligned)
#define BTILE    8
#define BTILES   (BATCH / BTILE)     // 8  -> grid = 37 x 8 = 296 = 2 CTAs/SM
#define THREADS  256

// Fast softplus: max(v,0) + log1p(exp(-|v|)) with MUFU intrinsics.
__device__ __forceinline__ float softplus_fast(float v) {
    float e = __expf(-fabsf(v));
    return fmaxf(v, 0.0f) + __logf(1.0f + e);
}

// ---------------------------------------------------------------------------
// Single kernel, o-split, 296-CTA balanced grid (2 CTAs per SM exactly).
// CTA (c, bt): o-chunk c (8 or 6 float4s, 32B-sector-aligned so no chunk
// overfetch), batches b0..b0+7, all 1024 i. Thread = (i-group, o4 lane):
//   C=8 -> G=32 groups of 32 i;  C=6 -> G=42 groups of 24/25 i (4 idle thr).
// 8 batch float4 accumulators per thread; i-loop unroll 4 for MLP.
// Epilogue: G-way i-group reduction in smem (reuses x tile), bias, store.
// No partials, no second kernel, fixed reduce order -> deterministic.
// ---------------------------------------------------------------------------
__global__ __launch_bounds__(THREADS) void bayes_kernel(
    const float* __restrict__ x,
    const float* __restrict__ mu,
    const float* __restrict__ ro,
    const float* __restrict__ eps,
    const float* __restrict__ mu_bias,
    const float* __restrict__ ro_bias,
    const float* __restrict__ eps_bias,
    float* __restrict__ out)
{
    const int c   = blockIdx.x;              // o-chunk 0..36
    const int bt  = blockIdx.y;              // 0..7
    const int b0  = bt * BTILE;
    const int C   = (c < NC8) ? 8 : 6;                      // float4s in chunk
    const int S   = (c < NC8) ? c * 8 : NC8 * 8 + (c - NC8) * 6; // chunk start (float4)
    const int G   = (c < NC8) ? 32 : 42;                    // i-groups
    const int t   = threadIdx.x;
    const bool act = (t < G * C);            // C=6: threads 252..255 idle
    const int ig  = act ? (t / C) : 0;
    const int o4l = act ? (t % C) : 0;
    const int o4g = S + o4l;                 // global float4 index along o

    // Balanced i-ranges over G groups.
    const int ibase = DIN / G;               // 32 or 24
    const int irem  = DIN % G;               // 0 or 16
    const int i_lo  = ig * ibase + min(ig, irem);
    const int len   = ibase + ((ig < irem) ? 1 : 0);

    // 32 KB shared: x tile [8][1024]; later reused as red[G][C][BTILE] float4
    // (max G*C*8*16 = 32*8*8*16 = 32768 B).
    __shared__ __align__(16) char s_mem[BTILE * DIN * 4];
    float*  sx  = reinterpret_cast<float*>(s_mem);   // sx[bb*DIN + i]
    float4* red = reinterpret_cast<float4*>(s_mem);  // red[ig*(C*8) + o4l*8 + bb]

    for (int idx = t; idx < BTILE * DIN; idx += THREADS)
        sx[idx] = x[(b0 + (idx >> 10)) * DIN + (idx & (DIN - 1))];
    __syncthreads();

    float4 acc[BTILE];
#pragma unroll
    for (int bb = 0; bb < BTILE; bb++) acc[bb] = make_float4(0.f, 0.f, 0.f, 0.f);

    const float4* ro4  = reinterpret_cast<const float4*>(ro);
    const float4* mu4  = reinterpret_cast<const float4*>(mu);
    const float4* eps4 = reinterpret_cast<const float4*>(eps);

    int row = i_lo * O4S + o4g;              // ro/mu float4 index
    int e0  = (b0 * DIN + i_lo) * O4S + o4g; // eps float4 index (<= 16.7M)

    if (act) {
#pragma unroll 4
        for (int k = 0; k < len; k++) {
            const int i = i_lo + k;
            const float4 r = ro4[row];
            const float4 m = mu4[row];
            float4 sg;
            sg.x = softplus_fast(r.x);
            sg.y = softplus_fast(r.y);
            sg.z = softplus_fast(r.z);
            sg.w = softplus_fast(r.w);
#pragma unroll
            for (int bb = 0; bb < BTILE; bb++) {
                const float  xv = sx[bb * DIN + i];
                const float4 e  = __ldcs(&eps4[e0 + bb * (DIN * O4S)]);
                acc[bb].x = fmaf(xv, fmaf(e.x, sg.x, m.x), acc[bb].x);
                acc[bb].y = fmaf(xv, fmaf(e.y, sg.y, m.y), acc[bb].y);
                acc[bb].z = fmaf(xv, fmaf(e.z, sg.z, m.z), acc[bb].z);
                acc[bb].w = fmaf(xv, fmaf(e.w, sg.w, m.w), acc[bb].w);
            }
            row += O4S;
            e0  += O4S;
        }
    }

    __syncthreads();                // all sx reads done before reusing s_mem
    if (act) {
#pragma unroll
        for (int bb = 0; bb < BTILE; bb++)
            red[ig * (C * BTILE) + o4l * BTILE + bb] = acc[bb];
    }
    __syncthreads();

    // Reduce G i-groups -> 8*C outputs. Fixed group order => deterministic.
    if (t < BTILE * C) {
        const int bb  = t / C;
        const int o4r = t % C;
        float4 sum = make_float4(0.f, 0.f, 0.f, 0.f);
        for (int g = 0; g < G; g++) {
            const float4 p = red[g * (C * BTILE) + o4r * BTILE + bb];
            sum.x += p.x; sum.y += p.y; sum.z += p.z; sum.w += p.w;
        }

        const int og = S + o4r;
        const int g4 = (b0 + bb) * O4S + og;
        const float4 rb = reinterpret_cast<const float4*>(ro_bias)[og];
        const float4 mb = reinterpret_cast<const float4*>(mu_bias)[og];
        const float4 eb = reinterpret_cast<const float4*>(eps_bias)[g4];

        float4 res;
        res.x = sum.x + fmaf(eb.x, softplus_fast(rb.x), mb.x);
        res.y = sum.y + fmaf(eb.y, softplus_fast(rb.y), mb.y);
        res.z = sum.z + fmaf(eb.z, softplus_fast(rb.z), mb.z);
        res.w = sum.w + fmaf(eb.w, softplus_fast(rb.w), mb.w);
        reinterpret_cast<float4*>(out)[g4] = res;
    }
}

// ---------------------------------------------------------------------------
// Launch. Inputs (metadata order): x, mu, ro, mu_bias, ro_bias, eps, eps_bias
// ---------------------------------------------------------------------------
extern "C" void kernel_launch(void* const* d_in, const int* in_sizes, int n_in,
                              void* d_out, int out_size) {
    const float* x        = (const float*)d_in[0];
    const float* mu       = (const float*)d_in[1];
    const float* ro       = (const float*)d_in[2];
    const float* mu_bias  = (const float*)d_in[3];
    const float* ro_bias  = (const float*)d_in[4];
    const float* eps      = (const float*)d_in[5];
    const float* eps_bias = (const float*)d_in[6];
    float* out = (float*)d_out;

    dim3 grid(OSPLITS, BTILES);
    bayes_kernel<<<grid, THREADS>>>(x, mu, ro, eps,
                                    mu_bias, ro_bias, eps_bias, out);
}

// round 17
// speedup vs baseline: 1.2556x; 1.2556x over previous
#include <cuda_runtime.h>
#include <math.h>

#define BATCH    64
#define DIN      1024
#define DOUT     1024
#define O4S      (DOUT / 4)          // 256 float4s along o
#define ISPLITS  18                  // grid = 18*16 = 288 CTAs (~2/SM)
#define CHUNK_HI 57                  // 16 chunks of 57
#define CHUNK_LO 56                  // 2 chunks of 56 (16*57+2*56 = 1024)
#define N_HI     16
#define BTILE    4
#define BTILES   (BATCH / BTILE)     // 16
#define THREADS  256                 // 256 threads * float4 = 1024 = DOUT

// Scratch (static __device__ global — allocation-free per harness rules)
__device__ float g_part[ISPLITS * BATCH * DOUT];   // 4.7 MB i-split partials

// Fast softplus: max(v,0) + log1p(exp(-|v|)) with MUFU intrinsics.
__device__ __forceinline__ float softplus_fast(float v) {
    float e = __expf(-fabsf(v));
    return fmaxf(v, 0.0f) + __logf(1.0f + e);
}

// ---------------------------------------------------------------------------
// Kernel 1 (main): champion structure (R8), smaller partials.
// grid = (ISPLITS, BTILES) = (18, 16) = 288 CTAs. Each CTA: 4 batches x
// {56|57} i-rows x all 1024 o. Thread: 4 consecutive o (uniform compile-time
// mapping — R16 lesson: runtime lane mapping kills load batching).
// eps evict-first (touched once); ro/mu default policy (16 concurrent
// readers -> L2 hits); partials default policy (small: 4.7 MB, partly
// L2-resident for the reduce).
// ---------------------------------------------------------------------------
__global__ __launch_bounds__(THREADS) void main_kernel(
    const float* __restrict__ x,
    const float* __restrict__ mu,
    const float* __restrict__ ro,
    const float* __restrict__ eps)
{
    const int ic  = blockIdx.x;          // i-chunk: 0..17
    const int bt  = blockIdx.y;          // b-tile:  0..15
    const int len = (ic < N_HI) ? CHUNK_HI : CHUNK_LO;
    const int i0  = (ic < N_HI) ? ic * CHUNK_HI
                                : N_HI * CHUNK_HI + (ic - N_HI) * CHUNK_LO;
    const int b0  = bt * BTILE;
    const int o4  = threadIdx.x;         // float4 index along o

    __shared__ float sx[BTILE][CHUNK_HI];   // 4 x 57 max
    {
        const int t = threadIdx.x;
        if (t < BTILE * len) {              // <= 228 < 256
            const int bb = t / len;
            const int ii = t % len;
            sx[bb][ii] = x[(b0 + bb) * DIN + i0 + ii];
        }
    }
    __syncthreads();

    float4 acc[BTILE];
#pragma unroll
    for (int bb = 0; bb < BTILE; bb++) acc[bb] = make_float4(0.f, 0.f, 0.f, 0.f);

    const float4* ro4  = reinterpret_cast<const float4*>(ro);
    const float4* mu4  = reinterpret_cast<const float4*>(mu);
    const float4* eps4 = reinterpret_cast<const float4*>(eps);

    int row   = i0 * O4S + o4;               // ro/mu float4 index
    int ebase = (b0 * DIN + i0) * O4S + o4;  // eps float4 index (<= 16.7M)

#pragma unroll 4
    for (int ii = 0; ii < len; ii++) {
        const float4 r = ro4[row];
        const float4 m = mu4[row];
        float4 sg;
        sg.x = softplus_fast(r.x);
        sg.y = softplus_fast(r.y);
        sg.z = softplus_fast(r.z);
        sg.w = softplus_fast(r.w);
#pragma unroll
        for (int bb = 0; bb < BTILE; bb++) {
            const float  xv = sx[bb][ii];
            const float4 e  = __ldcs(&eps4[ebase + bb * (DIN * O4S)]);
            acc[bb].x = fmaf(xv, fmaf(e.x, sg.x, m.x), acc[bb].x);
            acc[bb].y = fmaf(xv, fmaf(e.y, sg.y, m.y), acc[bb].y);
            acc[bb].z = fmaf(xv, fmaf(e.z, sg.z, m.z), acc[bb].z);
            acc[bb].w = fmaf(xv, fmaf(e.w, sg.w, m.w), acc[bb].w);
        }
        row   += O4S;
        ebase += O4S;
    }

    // Default store policy: partials small enough to partly stay in L2.
    float4* p4 = reinterpret_cast<float4*>(g_part);
#pragma unroll
    for (int bb = 0; bb < BTILE; bb++) {
        p4[(ic * BATCH + b0 + bb) * O4S + o4] = acc[bb];
    }
}

// ---------------------------------------------------------------------------
// Kernel 2: deterministic reduction over ISPLITS=18 partials + bias.
// 512 blocks x 256 threads. Block = 8 split-groups x 32 output-float4s;
// groups 0..5 sum 3 splits each (6*3=18), groups 6..7 contribute zero.
// Partial loads use default policy (hit L2 leftovers from main).
// ---------------------------------------------------------------------------
#define RED_GROUPS 8
#define RED_OUTS   32                // float4 outputs per block
#define SPG        3

__global__ __launch_bounds__(RED_GROUPS * RED_OUTS) void reduce_kernel(
    const float* __restrict__ mu_bias,
    const float* __restrict__ ro_bias,
    const float* __restrict__ eps_bias,
    float* __restrict__ out)
{
    const int t  = threadIdx.x & (RED_OUTS - 1);    // output lane within block
    const int g  = threadIdx.x / RED_OUTS;          // split group 0..7
    const int g4 = blockIdx.x * RED_OUTS + t;       // float4 idx over B*DOUT/4

    const float4* p4 = reinterpret_cast<const float4*>(g_part);

    const int s_lo = g * SPG;
    const int s_hi = min(ISPLITS, s_lo + SPG);      // groups 6,7: empty
    float4 sum = make_float4(0.f, 0.f, 0.f, 0.f);
    for (int s = s_lo; s < s_hi; s++) {
        const float4 p = p4[s * (BATCH * O4S) + g4];
        sum.x += p.x; sum.y += p.y; sum.z += p.z; sum.w += p.w;
    }

    __shared__ float4 red[RED_GROUPS][RED_OUTS];
    red[g][t] = sum;
    __syncthreads();

    if (g == 0) {
#pragma unroll
        for (int k = 1; k < RED_GROUPS; k++) {
            const float4 p = red[k][t];
            sum.x += p.x; sum.y += p.y; sum.z += p.z; sum.w += p.w;
        }
        const int o4 = g4 & (O4S - 1);
        const float4 rb = reinterpret_cast<const float4*>(ro_bias)[o4];
        const float4 mb = reinterpret_cast<const float4*>(mu_bias)[o4];
        const float4 eb = reinterpret_cast<const float4*>(eps_bias)[g4];

        float4 r;
        r.x = sum.x + fmaf(eb.x, softplus_fast(rb.x), mb.x);
        r.y = sum.y + fmaf(eb.y, softplus_fast(rb.y), mb.y);
        r.z = sum.z + fmaf(eb.z, softplus_fast(rb.z), mb.z);
        r.w = sum.w + fmaf(eb.w, softplus_fast(rb.w), mb.w);
        reinterpret_cast<float4*>(out)[g4] = r;
    }
}

// ---------------------------------------------------------------------------
// Launch. Inputs (metadata order): x, mu, ro, mu_bias, ro_bias, eps, eps_bias
// ---------------------------------------------------------------------------
extern "C" void kernel_launch(void* const* d_in, const int* in_sizes, int n_in,
                              void* d_out, int out_size) {
    const float* x        = (const float*)d_in[0];
    const float* mu       = (const float*)d_in[1];
    const float* ro       = (const float*)d_in[2];
    const float* mu_bias  = (const float*)d_in[3];
    const float* ro_bias  = (const float*)d_in[4];
    const float* eps      = (const float*)d_in[5];
    const float* eps_bias = (const float*)d_in[6];
    float* out = (float*)d_out;

    dim3 grid(ISPLITS, BTILES);
    main_kernel<<<grid, THREADS>>>(x, mu, ro, eps);

    reduce_kernel<<<(BATCH * O4S) / RED_OUTS, RED_GROUPS * RED_OUTS>>>(
        mu_bias, ro_bias, eps_bias, out);
}